// round 10
// baseline (speedup 1.0000x reference)
#include <cuda_runtime.h>
#include <cuda_bf16.h>
#include <cstdint>

#define NT 8192
#define THRESH 0.7f

// -------- global scratch (allocation-free rule) --------
__device__ __nv_bfloat16 g_Mhi[NT * 64];   // (U@W) split hi, [i][f]
__device__ __nv_bfloat16 g_Mlo[NT * 64];
__device__ __nv_bfloat16 g_Uhi[NT * 64];   // U split hi, [j][f]
__device__ __nv_bfloat16 g_Ulo[NT * 64];
__device__ __nv_bfloat16 g_Vthi[128 * NT]; // gated V^T split hi, [c=b*64+d][i]
__device__ __nv_bfloat16 g_Vtlo[128 * NT];

// -------- helpers --------
__device__ __forceinline__ uint32_t smem_u32(const void* p) {
    uint32_t a;
    asm("{ .reg .u64 t; cvta.to.shared.u64 t, %1; cvt.u32.u64 %0, t; }"
        : "=r"(a) : "l"(p));
    return a;
}
__device__ __forceinline__ void cpasync16(uint32_t saddr, const void* g) {
    asm volatile("cp.async.cg.shared.global [%0], [%1], 16;\n" :: "r"(saddr), "l"(g));
}
#define CP_COMMIT()  asm volatile("cp.async.commit_group;\n" ::: "memory")
#define CP_WAIT0()   asm volatile("cp.async.wait_group 0;\n" ::: "memory")
#define CP_WAIT1()   asm volatile("cp.async.wait_group 1;\n" ::: "memory")

__device__ __forceinline__ void ldsm4(uint32_t* r, uint32_t a) {
    asm volatile("ldmatrix.sync.aligned.m8n8.x4.shared.b16 {%0,%1,%2,%3}, [%4];"
                 : "=r"(r[0]), "=r"(r[1]), "=r"(r[2]), "=r"(r[3]) : "r"(a));
}
__device__ __forceinline__ void mma_bf16(float* c, const uint32_t* a,
                                         uint32_t b0, uint32_t b1) {
    asm volatile("mma.sync.aligned.m16n8k16.row.col.f32.bf16.bf16.f32 "
                 "{%0,%1,%2,%3}, {%4,%5,%6,%7}, {%8,%9}, {%0,%1,%2,%3};"
                 : "+f"(c[0]), "+f"(c[1]), "+f"(c[2]), "+f"(c[3])
                 : "r"(a[0]), "r"(a[1]), "r"(a[2]), "r"(a[3]), "r"(b0), "r"(b1));
}
__device__ __forceinline__ uint32_t packbf2(float a, float b) {
    uint32_t r;
    asm("cvt.rn.bf16x2.f32 %0, %1, %2;" : "=r"(r) : "f"(a), "f"(b));
    return r;
}
__device__ __forceinline__ float fast_sigmoid(float x) {
    float e, r;
    asm("ex2.approx.f32 %0, %1;" : "=f"(e) : "f"(-1.44269504f * x));
    asm("rcp.approx.f32 %0, %1;" : "=f"(r) : "f"(1.0f + e));
    return r;
}
__device__ __forceinline__ void bf16split(float x, __nv_bfloat16& hi, __nv_bfloat16& lo) {
    hi = __float2bfloat16_rn(x);
    lo = __float2bfloat16_rn(x - __bfloat162float(hi));
}

// -------- SMEM layout (bytes) --------
#define OFF_UHI 0u          //  8KB
#define OFF_ULO 8192u       //  8KB
#define OFF_M0  16384u      //  2 bufs x (hi 8KB + lo 8KB) = 32KB
#define OFF_PHI 49152u      //  8KB
#define OFF_PLO 57344u      //  8KB
#define OFF_V0  65536u      //  2 bufs x (hi 16KB + lo 16KB) = 64KB
#define SMEM_TOTAL 131072u  // 128KB

// ============ prep: M = U@W, bf16 splits of M and U (i-tile 32) ============
__global__ void prep_mu_kernel(const float* __restrict__ U,
                               const float* __restrict__ W) {
    __shared__ float ws[64 * 64];
    __shared__ float us[32 * 64];
    const int tid = threadIdx.x;
    const int i0  = blockIdx.x * 32;
    #pragma unroll
    for (int k = 0; k < 4; ++k)
        ((float4*)ws)[tid + k * 256] = ((const float4*)W)[tid + k * 256];
    #pragma unroll
    for (int k = 0; k < 2; ++k)
        ((float4*)us)[tid + k * 256] =
            ((const float4*)(U + (size_t)i0 * 64))[tid + k * 256];
    __syncthreads();
    #pragma unroll
    for (int t = 0; t < 8; ++t) {
        int idx = t * 256 + tid;
        int il = idx >> 6, f = idx & 63;
        float s0 = 0.f, s1 = 0.f, s2 = 0.f, s3 = 0.f;
        #pragma unroll
        for (int e = 0; e < 64; e += 4) {
            s0 += us[il * 64 + e]     * ws[e * 64 + f];
            s1 += us[il * 64 + e + 1] * ws[(e + 1) * 64 + f];
            s2 += us[il * 64 + e + 2] * ws[(e + 2) * 64 + f];
            s3 += us[il * 64 + e + 3] * ws[(e + 3) * 64 + f];
        }
        float sum = (s0 + s1) + (s2 + s3);
        __nv_bfloat16 hi, lo;
        bf16split(sum, hi, lo);
        size_t o = (size_t)(i0 + il) * 64 + f;
        g_Mhi[o] = hi; g_Mlo[o] = lo;
        bf16split(us[il * 64 + f], hi, lo);
        g_Uhi[o] = hi; g_Ulo[o] = lo;
    }
}

// ============ prep: V^T[c][i] = relu(prof-thr)*state, bf16 split (i-tile 32) ============
__global__ void prep_v_kernel(const float* __restrict__ states,
                              const float* __restrict__ prof) {
    __shared__ float sv[32 * 128];   // [il][c]
    const int tid = threadIdx.x;
    const int i0  = blockIdx.x * 32;
    #pragma unroll
    for (int k = 0; k < 4; ++k) {
        int idx = tid + k * 256;       // 1024 float4s
        int il = idx >> 5, q = idx & 31;
        int c0 = q * 4, b = c0 >> 6, d = c0 & 63;
        float g = fmaxf(prof[b * NT + i0 + il] - THRESH, 0.f);
        float4 st = *(const float4*)&states[((size_t)b * NT + i0 + il) * 64 + d];
        float4 o; o.x = st.x * g; o.y = st.y * g; o.z = st.z * g; o.w = st.w * g;
        *(float4*)&sv[il * 128 + c0] = o;
    }
    __syncthreads();
    #pragma unroll
    for (int k = 0; k < 2; ++k) {
        int idx = tid + k * 256;       // 512 chunks
        int c = idx >> 2, ic = idx & 3;
        int ib = ic * 8;
        union { uint4 u; __nv_bfloat16 h[8]; } ph, pl;
        #pragma unroll
        for (int r = 0; r < 8; ++r) {
            __nv_bfloat16 hi, lo;
            bf16split(sv[(ib + r) * 128 + c], hi, lo);
            ph.h[r] = hi; pl.h[r] = lo;
        }
        size_t o = (size_t)c * NT + i0 + ib;
        *(uint4*)&g_Vthi[o] = ph.u;
        *(uint4*)&g_Vtlo[o] = pl.u;
    }
}

// ---- one kk-step of phase A: accA += Ufrag(kk) x M-frag(kk), 3 split terms ----
// U fragments are register-hoisted (uH/uL).
#define A_KK(ACC, MB, KK) do {                                                   \
    uint32_t _aoff = (uint32_t)((((KK) * 2 + colsel) ^ x7) << 4);                \
    _Pragma("unroll")                                                            \
    for (int _p = 0; _p < 2; ++_p) {                                             \
        uint32_t _bb = (MB) + (uint32_t)(ib2 + _p * 16 + row16) * 128 + _aoff;   \
        uint32_t _bH[4], _bL[4];                                                 \
        ldsm4(_bH, _bb);                                                         \
        ldsm4(_bL, _bb + 8192u);                                                 \
        mma_bf16(ACC[2 * _p],     uH[KK], _bH[0], _bH[2]);                       \
        mma_bf16(ACC[2 * _p],     uH[KK], _bL[0], _bL[2]);                       \
        mma_bf16(ACC[2 * _p],     uL[KK], _bH[0], _bH[2]);                       \
        mma_bf16(ACC[2 * _p + 1], uH[KK], _bH[1], _bH[3]);                       \
        mma_bf16(ACC[2 * _p + 1], uH[KK], _bL[1], _bL[3]);                       \
        mma_bf16(ACC[2 * _p + 1], uL[KK], _bH[1], _bH[3]);                       \
    }                                                                            \
} while (0)

// ---- epilogue quarter: 4 values of S -> sigmoid/mask -> P^T hi/lo stores ----
#define EPI_NB(ACC, NB, T) do {                                                  \
    int _i00 = ib2 + (NB) * 8 + 2 * t4;                                          \
    float _p00 = fast_sigmoid(ACC[NB][0] + bias);                                \
    float _p01 = fast_sigmoid(ACC[NB][1] + bias);                                \
    float _p10 = fast_sigmoid(ACC[NB][2] + bias);                                \
    float _p11 = fast_sigmoid(ACC[NB][3] + bias);                                \
    if ((T) == tdiag) {                                                          \
        if (_i00     == j1) _p00 = 0.f;                                          \
        if (_i00 + 1 == j1) _p01 = 0.f;                                          \
        if (_i00     == j2) _p10 = 0.f;                                          \
        if (_i00 + 1 == j2) _p11 = 0.f;                                          \
    }                                                                            \
    int _c8 = _i00 >> 3;                                                         \
    uint32_t _a1 = OFF_PHI + (uint32_t)(j1 * 128 + ((_c8 ^ (j1 & 7)) << 4) + t4 * 4); \
    uint32_t _a2 = OFF_PHI + (uint32_t)(j2 * 128 + ((_c8 ^ (j2 & 7)) << 4) + t4 * 4); \
    uint32_t _h1 = packbf2(_p01, _p00);                                          \
    uint32_t _h2 = packbf2(_p11, _p10);                                          \
    float _r00 = _p00 - __uint_as_float(_h1 << 16);                              \
    float _r01 = _p01 - __uint_as_float(_h1 & 0xffff0000u);                      \
    float _r10 = _p10 - __uint_as_float(_h2 << 16);                              \
    float _r11 = _p11 - __uint_as_float(_h2 & 0xffff0000u);                      \
    *(uint32_t*)(smem + _a1)         = _h1;                                      \
    *(uint32_t*)(smem + _a2)         = _h2;                                      \
    *(uint32_t*)(smem + _a1 + 8192u) = packbf2(_r01, _r00);                      \
    *(uint32_t*)(smem + _a2 + 8192u) = packbf2(_r11, _r10);                      \
} while (0)

// ---- full phase B: accB += V^T(t) x P(t), 3 split terms; 4c x 2j partition ----
// Per warp: c-rows [cbB, cbB+32), j-cols [jhB, jhB+32).
#define PHASE_B(VB) do {                                                         \
    _Pragma("unroll")                                                            \
    for (int _kk = 0; _kk < 4; ++_kk) {                                          \
        uint32_t _aoff = (uint32_t)(((_kk * 2 + colsel) ^ x7) << 4);             \
        uint32_t _vH[2][4], _vL[2][4], _pH[2][4], _pL[2][4];                     \
        _Pragma("unroll")                                                        \
        for (int _m = 0; _m < 2; ++_m) {                                         \
            uint32_t _va = (VB) + (uint32_t)(cbB + _m * 16 + row16) * 128 + _aoff; \
            ldsm4(_vH[_m], _va);                                                 \
            ldsm4(_vL[_m], _va + 16384u);                                        \
        }                                                                        \
        _Pragma("unroll")                                                        \
        for (int _p = 0; _p < 2; ++_p) {                                         \
            uint32_t _pa = sb + OFF_PHI + (uint32_t)(jhB + _p * 16 + row16) * 128 + _aoff; \
            ldsm4(_pH[_p], _pa);                                                 \
            ldsm4(_pL[_p], _pa + 8192u);                                         \
        }                                                                        \
        _Pragma("unroll")                                                        \
        for (int _m = 0; _m < 2; ++_m) {                                         \
            _Pragma("unroll")                                                    \
            for (int _p = 0; _p < 2; ++_p) {                                     \
                mma_bf16(accB[_m][2 * _p],     _vH[_m], _pH[_p][0], _pH[_p][2]); \
                mma_bf16(accB[_m][2 * _p],     _vH[_m], _pL[_p][0], _pL[_p][2]); \
                mma_bf16(accB[_m][2 * _p],     _vL[_m], _pH[_p][0], _pH[_p][2]); \
                mma_bf16(accB[_m][2 * _p + 1], _vH[_m], _pH[_p][1], _pH[_p][3]); \
                mma_bf16(accB[_m][2 * _p + 1], _vH[_m], _pL[_p][1], _pL[_p][3]); \
                mma_bf16(accB[_m][2 * _p + 1], _vL[_m], _pH[_p][1], _pH[_p][3]); \
            }                                                                    \
        }                                                                        \
    }                                                                            \
} while (0)

// ---- one pipeline step: epilogue(T) interleaved with phase A(T+1), then B(T) ----
#define BODY(T, CUR, NXT) do {                                                   \
    CP_WAIT0();                                                                  \
    __syncthreads();                                                             \
    if ((T) + 1 < 128) {                                                         \
        prefV((T) + 1);                                                          \
        if ((T) + 2 < 128) prefM((T) + 2);                                       \
        CP_COMMIT();                                                             \
    }                                                                            \
    const uint32_t _mbN = sb + OFF_M0 + (uint32_t)((((T) + 1) & 1)) * 16384u;    \
    const bool _doA = ((T) + 1 < 128);                                           \
    if (_doA) {                                                                  \
        _Pragma("unroll")                                                        \
        for (int _z = 0; _z < 4; ++_z) {                                         \
            NXT[_z][0] = 0.f; NXT[_z][1] = 0.f; NXT[_z][2] = 0.f; NXT[_z][3] = 0.f; \
        }                                                                        \
        A_KK(NXT, _mbN, 0);                                                      \
    }                                                                            \
    EPI_NB(CUR, 0, T);                                                           \
    if (_doA) A_KK(NXT, _mbN, 1);                                                \
    EPI_NB(CUR, 1, T);                                                           \
    if (_doA) A_KK(NXT, _mbN, 2);                                                \
    EPI_NB(CUR, 2, T);                                                           \
    if (_doA) A_KK(NXT, _mbN, 3);                                                \
    EPI_NB(CUR, 3, T);                                                           \
    __syncthreads();                                                             \
    PHASE_B(sb + OFF_V0 + (uint32_t)(((T) & 1)) * 32768u);                       \
} while (0)

// ============ main fused kernel (HMMA, pipelined, i-tile 64) ============
extern __shared__ char smem[];
__global__ void __launch_bounds__(256, 1)
dyadic_hmma_kernel(const float* __restrict__ states,
                   const float* __restrict__ bias_ptr,
                   float* __restrict__ out) {
    const uint32_t sb = smem_u32(smem);
    const int tid = threadIdx.x;
    const int wid = tid >> 5;
    const int l   = tid & 31;
    const int j0  = blockIdx.x * 64;
    const int tdiag = blockIdx.x;

    const int row16  = ((l >> 3) & 1) * 8 + (l & 7);
    const int colsel = l >> 4;
    const int x7 = l & 7;
    const int g  = l >> 2;
    const int t4 = l & 3;

    const int jb  = (wid & 3) * 16;   // phase A: j rows
    const int ib2 = (wid >> 2) * 32;  // phase A: i cols
    const int j1  = jb + g, j2 = j1 + 8;

    const int cbB = (wid & 3) * 32;   // phase B: c rows (4-way)
    const int jhB = (wid >> 2) * 32;  // phase B: j half (2-way)

    // ---- persistent U tile (plain loads) ----
    #pragma unroll
    for (int k = 0; k < 2; ++k) {
        int q = tid + k * 256;               // 512 chunks per half
        int r = q >> 3, c16 = q & 7;
        uint32_t d = (uint32_t)(r * 128 + ((c16 ^ (r & 7)) << 4));
        *(uint4*)(smem + OFF_UHI + d) = *(const uint4*)&g_Uhi[(size_t)(j0 + r) * 64 + c16 * 8];
        *(uint4*)(smem + OFF_ULO + d) = *(const uint4*)&g_Ulo[(size_t)(j0 + r) * 64 + c16 * 8];
    }

    auto prefM = [&](int tt) {               // M(tt) -> buf tt&1
        const uint32_t mb = sb + OFF_M0 + (uint32_t)(tt & 1) * 16384u;
        const size_t gi0 = (size_t)(tt << 6) * 64;
        #pragma unroll
        for (int k = 0; k < 2; ++k) {
            int q = tid + k * 256;           // 512 chunks per half
            int r = q >> 3, c16 = q & 7;
            uint32_t d = (uint32_t)(r * 128 + ((c16 ^ (r & 7)) << 4));
            cpasync16(mb + d,         &g_Mhi[gi0 + (size_t)r * 64 + c16 * 8]);
            cpasync16(mb + 8192u + d, &g_Mlo[gi0 + (size_t)r * 64 + c16 * 8]);
        }
    };
    auto prefV = [&](int tt) {               // V(tt) -> buf tt&1
        const uint32_t vb = sb + OFF_V0 + (uint32_t)(tt & 1) * 32768u;
        const int i0g = tt << 6;
        #pragma unroll
        for (int k = 0; k < 4; ++k) {
            int q = tid + k * 256;           // 1024 chunks per half
            int c = q >> 3, c16 = q & 7;
            uint32_t d = (uint32_t)(c * 128 + ((c16 ^ (c & 7)) << 4));
            cpasync16(vb + d,          &g_Vthi[(size_t)c * NT + i0g + c16 * 8]);
            cpasync16(vb + 16384u + d, &g_Vtlo[(size_t)c * NT + i0g + c16 * 8]);
        }
    };

    // prologue: M(0) | {V(0), M(1)}
    prefM(0);
    CP_COMMIT();
    prefV(0);
    prefM(1);
    CP_COMMIT();
    CP_WAIT1();          // M(0) ready
    __syncthreads();

    const float bias = __ldg(bias_ptr);
    const uint32_t uAbase = sb + OFF_UHI + (uint32_t)(jb + row16) * 128;

    // ---- hoist U fragments into registers (4 kk x hi/lo) ----
    uint32_t uH[4][4], uL[4][4];
    #pragma unroll
    for (int kk = 0; kk < 4; ++kk) {
        uint32_t aoff = (uint32_t)(((kk * 2 + colsel) ^ x7) << 4);
        ldsm4(uH[kk], uAbase + aoff);
        ldsm4(uL[kk], uAbase + 8192u + aoff);
    }

    float accB[2][4][4];
    #pragma unroll
    for (int m = 0; m < 2; ++m)
        #pragma unroll
        for (int n = 0; n < 4; ++n)
            #pragma unroll
            for (int v = 0; v < 4; ++v) accB[m][n][v] = 0.f;

    float accX[4][4], accY[4][4];
    // phase A(0) -> accX
    {
        #pragma unroll
        for (int z = 0; z < 4; ++z) {
            accX[z][0] = 0.f; accX[z][1] = 0.f; accX[z][2] = 0.f; accX[z][3] = 0.f;
        }
        const uint32_t mb0 = sb + OFF_M0;
        A_KK(accX, mb0, 0);
        A_KK(accX, mb0, 1);
        A_KK(accX, mb0, 2);
        A_KK(accX, mb0, 3);
    }

    for (int t = 0; t < 128; t += 2) {
        BODY(t, accX, accY);
        BODY(t + 1, accY, accX);
    }

    // ---- final epilogue: out = state + leaked ----
    #pragma unroll
    for (int m = 0; m < 2; ++m) {
        const int c1 = cbB + m * 16 + g, c2 = c1 + 8;
        const int b1 = c1 >> 6, d1 = c1 & 63;
        const int b2 = c2 >> 6, d2 = c2 & 63;
        #pragma unroll
        for (int n = 0; n < 4; ++n) {
            int j = j0 + jhB + n * 8 + 2 * t4;
            size_t o1 = ((size_t)b1 * NT + j) * 64 + d1;
            size_t o2 = ((size_t)b2 * NT + j) * 64 + d2;
            out[o1]      = states[o1]      + accB[m][n][0];
            out[o1 + 64] = states[o1 + 64] + accB[m][n][1];
            out[o2]      = states[o2]      + accB[m][n][2];
            out[o2 + 64] = states[o2 + 64] + accB[m][n][3];
        }
    }
}

extern "C" void kernel_launch(void* const* d_in, const int* in_sizes, int n_in,
                              void* d_out, int out_size) {
    const float* states = (const float*)d_in[0];  // [2, 8192, 64]
    const float* prof   = (const float*)d_in[1];  // [2, 8192]
    const float* U      = (const float*)d_in[2];  // [8192, 64]
    const float* W      = (const float*)d_in[3];  // [1, 64, 64]
    const float* bias   = (const float*)d_in[4];  // [1]
    float* out = (float*)d_out;

    cudaFuncSetAttribute(dyadic_hmma_kernel,
                         cudaFuncAttributeMaxDynamicSharedMemorySize, SMEM_TOTAL);

    prep_mu_kernel<<<NT / 32, 256>>>(U, W);
    prep_v_kernel<<<NT / 32, 256>>>(states, prof);
    dyadic_hmma_kernel<<<NT / 64, 256, SMEM_TOTAL>>>(states, bias, out);
}